// round 7
// baseline (speedup 1.0000x reference)
#include <cuda_runtime.h>
#include <cuda_bf16.h>
#include <cstdint>

// ---------------- constants ----------------
#define N0 8000
#define N1 64000
#define N2 512000
#define NBLK_STATS 512

// ---------------- device scratch (no allocations allowed) ----------------
__device__ float g_t1[N1 * 96];        // layer1 out  [64000, 96]
__device__ float g_t2[N1 * 64];        // layer2 out  [64000, 64]
__device__ float g_t3[N2 * 64];        // layer3 out  [512000, 64]
__device__ float g_t4[N2 * 32];        // layer4 out  [512000, 32]
__device__ float g_w2a[128 * 8 * 96];  // permuted w_tr1 -> [128, 768]
__device__ float g_w2b[64 * 8 * 64];   // permuted w_tr2 -> [64, 512]
__device__ float g_wf1[27 * 96 * 64];  // w_c1 in tf32 fragment order
__device__ float g_wf2[27 * 64 * 32];  // w_c2 in tf32 fragment order
__device__ float g_part[NBLK_STATS * 2 * 96];
__device__ float g_ab[2 * 96];         // folded BN scale/shift

// ---------------- helpers ----------------
__device__ __forceinline__ uint32_t f2tf32(float f) {
    uint32_t u;
    asm("cvt.rna.tf32.f32 %0, %1;" : "=r"(u) : "f"(f));
    return u;
}

__device__ __forceinline__ void mma_tf32(float c[4], uint32_t a0, uint32_t a1,
                                         uint32_t a2, uint32_t a3,
                                         uint32_t b0, uint32_t b1) {
    asm("mma.sync.aligned.m16n8k8.row.col.f32.tf32.tf32.f32 "
        "{%0,%1,%2,%3},{%4,%5,%6,%7},{%8,%9},{%0,%1,%2,%3};"
        : "+f"(c[0]), "+f"(c[1]), "+f"(c[2]), "+f"(c[3])
        : "r"(a0), "r"(a1), "r"(a2), "r"(a3), "r"(b0), "r"(b1));
}

// ---------------- weight permute: w[k,c,d] -> W2[c, k*D+d] ----------------
__global__ void permute_w_kernel(const float* __restrict__ w, float* __restrict__ W2,
                                 int KK, int Cin, int D) {
    int t = blockIdx.x * blockDim.x + threadIdx.x;
    int tot = KK * Cin * D;
    if (t >= tot) return;
    int d = t % D;
    int c = (t / D) % Cin;
    int k = t / (D * Cin);
    W2[c * (KK * D) + k * D + d] = w[t];
}

// ---------------- wfrag prep: w[27,CIN,COUT] -> tf32 fragment order -------------
// wf[((k*KS + kk)*NFT + nf)*64 + lane*2 + {0,1}]
//   b0 = w[k][kk*8 + lane%4    ][nf*8 + lane/4]
//   b1 = w[k][kk*8 + lane%4 + 4][nf*8 + lane/4]
__global__ void wfrag_kernel(const float* __restrict__ w, float* __restrict__ wf,
                             int CIN, int COUT) {
    int t = blockIdx.x * blockDim.x + threadIdx.x;
    int KS = CIN / 8, NFT = COUT / 8;
    int tot = 27 * KS * NFT * 32;
    if (t >= tot) return;
    int lane = t & 31;
    int rest = t >> 5;
    int nf = rest % NFT; rest /= NFT;
    int kk = rest % KS;
    int k = rest / KS;
    int row = kk * 8 + (lane & 3);
    int col = nf * 8 + (lane >> 2);
    const float* wk = w + (size_t)k * CIN * COUT;
    wf[2 * t + 0] = __uint_as_float(f2tf32(wk[(size_t)row * COUT + col]));
    wf[2 * t + 1] = __uint_as_float(f2tf32(wk[(size_t)(row + 4) * COUT + col]));
}

// ---------------- fp32 tiled GEMM: C[M,N] = A[M,K] @ B[K,N] ----------------
#define GBM 64
#define GBN 64
#define GBK 16
#define GPITCH 68
__global__ __launch_bounds__(256) void gemm_kernel(const float* __restrict__ A,
                                                   const float* __restrict__ B,
                                                   float* __restrict__ C,
                                                   int M, int N, int K) {
    __shared__ __align__(16) float As[GBK][GPITCH];
    __shared__ __align__(16) float Bs[GBK][GBN];
    const int tid = threadIdx.x;
    const int tx = tid % 16;
    const int ty = tid / 16;
    const int rowBase = blockIdx.y * GBM;
    const int colBase = blockIdx.x * GBN;
    float acc[4][4] = {};
    for (int k0 = 0; k0 < K; k0 += GBK) {
        #pragma unroll
        for (int t = tid; t < GBM * GBK; t += 256) {
            int c = t % GBK, r = t / GBK;
            int gr = rowBase + r, gc = k0 + c;
            As[c][r] = (gr < M && gc < K) ? A[(size_t)gr * K + gc] : 0.f;
        }
        #pragma unroll
        for (int t = tid; t < GBK * GBN; t += 256) {
            int c = t % GBN, r = t / GBN;
            int gr = k0 + r, gc = colBase + c;
            Bs[r][c] = (gr < K && gc < N) ? B[(size_t)gr * N + gc] : 0.f;
        }
        __syncthreads();
        #pragma unroll
        for (int kk = 0; kk < GBK; kk++) {
            float4 av = *reinterpret_cast<const float4*>(&As[kk][ty * 4]);
            float4 bv = *reinterpret_cast<const float4*>(&Bs[kk][tx * 4]);
            float a[4] = {av.x, av.y, av.z, av.w};
            float b[4] = {bv.x, bv.y, bv.z, bv.w};
            #pragma unroll
            for (int i = 0; i < 4; i++)
                #pragma unroll
                for (int j = 0; j < 4; j++) acc[i][j] = fmaf(a[i], b[j], acc[i][j]);
        }
        __syncthreads();
    }
    #pragma unroll
    for (int i = 0; i < 4; i++) {
        int gr = rowBase + ty * 4 + i;
        if (gr >= M) continue;
        #pragma unroll
        for (int j = 0; j < 4; j++) {
            int gc = colBase + tx * 4 + j;
            if (gc < N) C[(size_t)gr * N + gc] = acc[i][j];
        }
    }
}

// ---------------- BN stats: per-block column sum/sumsq, float4, deterministic ------
__global__ void stats4_kernel(const float* __restrict__ X, int nrows, int C,
                              float* __restrict__ part) {
    extern __shared__ float sm[];
    const int C4 = C >> 2;
    const int c4 = threadIdx.x;
    const int ty = threadIdx.y;
    const int TY = blockDim.y;
    const float4* X4 = reinterpret_cast<const float4*>(X);
    float s0 = 0.f, s1 = 0.f, s2 = 0.f, s3 = 0.f;
    float q0 = 0.f, q1 = 0.f, q2 = 0.f, q3 = 0.f;
    for (int n = blockIdx.x * TY + ty; n < nrows; n += gridDim.x * TY) {
        float4 v = X4[(size_t)n * C4 + c4];
        s0 += v.x; q0 = fmaf(v.x, v.x, q0);
        s1 += v.y; q1 = fmaf(v.y, v.y, q1);
        s2 += v.z; q2 = fmaf(v.z, v.z, q2);
        s3 += v.w; q3 = fmaf(v.w, v.w, q3);
    }
    float* S = sm;
    float* Q = sm + TY * C;
    int cb = c4 * 4;
    S[ty * C + cb + 0] = s0; S[ty * C + cb + 1] = s1;
    S[ty * C + cb + 2] = s2; S[ty * C + cb + 3] = s3;
    Q[ty * C + cb + 0] = q0; Q[ty * C + cb + 1] = q1;
    Q[ty * C + cb + 2] = q2; Q[ty * C + cb + 3] = q3;
    __syncthreads();
    int tid = ty * C4 + c4;
    if (tid < C) {
        float s = 0.f, q = 0.f;
        for (int t = 0; t < TY; t++) { s += S[t * C + tid]; q += Q[t * C + tid]; }
        part[blockIdx.x * 2 * C + tid] = s;
        part[blockIdx.x * 2 * C + C + tid] = q;
    }
}

// ---------------- finalize: fold BN into a[c], b'[c] ----------------
__global__ void finalize_kernel(const float* __restrict__ part, int nblk, int C,
                                float invN, const float* __restrict__ g,
                                const float* __restrict__ b, float* __restrict__ ab) {
    int c = threadIdx.x;
    if (c >= C) return;
    float s = 0.f, q = 0.f;
    #pragma unroll 8
    for (int i = 0; i < nblk; i++) {
        s += part[i * 2 * C + c];
        q += part[i * 2 * C + C + c];
    }
    float mean = s * invN;
    float var = q * invN - mean * mean;
    float rstd = rsqrtf(var + 1e-5f);
    float a = g[c] * rstd;
    ab[c] = a;
    ab[C + c] = b[c] - mean * a;
}

// ---------------- BN apply + ReLU (in place, float4) ----------------
__global__ void bnrelu4_kernel(float* __restrict__ X, const float* __restrict__ ab,
                               int total4, int C) {
    int t = blockIdx.x * blockDim.x + threadIdx.x;
    if (t >= total4) return;
    int C4 = C >> 2;
    int c = (t % C4) * 4;
    float4 v = reinterpret_cast<float4*>(X)[t];
    v.x = fmaxf(fmaf(v.x, __ldg(ab + c + 0), __ldg(ab + C + c + 0)), 0.f);
    v.y = fmaxf(fmaf(v.y, __ldg(ab + c + 1), __ldg(ab + C + c + 1)), 0.f);
    v.z = fmaxf(fmaf(v.z, __ldg(ab + c + 2), __ldg(ab + C + c + 2)), 0.f);
    v.w = fmaxf(fmaf(v.w, __ldg(ab + c + 3), __ldg(ab + C + c + 3)), 0.f);
    reinterpret_cast<float4*>(X)[t] = v;
}

// ---------------- BN apply + ReLU + row-mean (layer 4, C=32) ----------------
__global__ void bnrelu_rowmean32_kernel(float* __restrict__ X, const float* __restrict__ ab,
                                        float* __restrict__ intensity, int N) {
    int gw = (blockIdx.x * blockDim.x + threadIdx.x) >> 5;
    int lane = threadIdx.x & 31;
    if (gw >= N) return;
    float v = fmaxf(fmaf(X[(size_t)gw * 32 + lane], ab[lane], ab[32 + lane]), 0.f);
    X[(size_t)gw * 32 + lane] = v;
    float s = v;
    #pragma unroll
    for (int o = 16; o; o >>= 1) s += __shfl_xor_sync(0xFFFFFFFFu, s, o);
    if (lane == 0) intensity[gw] = s * (1.f / 32.f);
}

// ---------------- conv3 via tf32 mma.sync gather-GEMM ----------------------
// Block: BM rows. 8 warps, each computes a 32 x (COUT/NWARP) tile.
// Per offset k: gather BM rows (mask-scaled, tf32-rounded) into SMEM As
// [BM][CIN+4], stage pre-fragmented W[k] slice, run m16n8k8 MMAs.
template <int CIN, int COUT, int BM, int NWARP>
__global__ __launch_bounds__(256) void conv3mma_kernel(
    const float* __restrict__ X, const int* __restrict__ idx,
    const float* __restrict__ mask, const float* __restrict__ Wf,
    float* __restrict__ out, int N) {
    constexpr int PITCH = CIN + 4;
    constexpr int C4 = CIN / 4;
    constexpr int KS = CIN / 8;
    constexpr int NFT = COUT / 8;
    constexpr int NPW = COUT / NWARP;   // cols per warp
    constexpr int NF = NPW / 8;         // n-frags per warp
    constexpr int ROWTILES = BM / 32;
    static_assert(ROWTILES * NWARP == 8, "need 8 warps");

    extern __shared__ __align__(16) char smem_raw[];
    uint32_t* As = reinterpret_cast<uint32_t*>(smem_raw);            // BM*PITCH
    float* Wfs = reinterpret_cast<float*>(As + BM * PITCH);          // CIN*COUT
    int* ridx = reinterpret_cast<int*>(Wfs + CIN * COUT);            // BM
    float* rmask = reinterpret_cast<float*>(ridx + BM);              // BM

    const int tid = threadIdx.x;
    const int w = tid >> 5;
    const int lane = tid & 31;
    const int lr = lane >> 2;   // groupID
    const int lc = lane & 3;    // thread in group
    const int rowtile = w / NWARP;
    const int nhalf = w % NWARP;
    const int rowbase = rowtile * 32;
    const int n0 = blockIdx.x * BM;
    const float4* X4 = reinterpret_cast<const float4*>(X);

    float acc[2][NF][4];
    #pragma unroll
    for (int mf = 0; mf < 2; mf++)
        #pragma unroll
        for (int nf = 0; nf < NF; nf++)
            #pragma unroll
            for (int i = 0; i < 4; i++) acc[mf][nf][i] = 0.f;

    for (int k = 0; k < 27; k++) {
        __syncthreads();  // previous compute done; As/Wfs/ridx reusable
        if (tid < BM) {
            int n = n0 + tid;
            ridx[tid] = idx[(size_t)k * N + n];
            rmask[tid] = mask[(size_t)k * N + n];
        }
        {
            const float4* src = reinterpret_cast<const float4*>(Wf + (size_t)k * CIN * COUT);
            float4* dst = reinterpret_cast<float4*>(Wfs);
            #pragma unroll
            for (int t = tid; t < CIN * COUT / 4; t += 256) dst[t] = src[t];
        }
        __syncthreads();  // ridx/rmask visible
        // gather + mask + tf32 round
        #pragma unroll
        for (int t = tid; t < BM * C4; t += 256) {
            int r = t / C4, c4 = t % C4;
            float4 v = X4[(size_t)ridx[r] * C4 + c4];
            float m = rmask[r];
            uint4 u;
            u.x = f2tf32(v.x * m);
            u.y = f2tf32(v.y * m);
            u.z = f2tf32(v.z * m);
            u.w = f2tf32(v.w * m);
            *reinterpret_cast<uint4*>(As + r * PITCH + c4 * 4) = u;
        }
        __syncthreads();  // As visible
        // MMA over K
        const uint2* Wu = reinterpret_cast<const uint2*>(Wfs);
        #pragma unroll
        for (int ks = 0; ks < KS; ks++) {
            uint32_t a[2][4];
            #pragma unroll
            for (int mf = 0; mf < 2; mf++) {
                int base = (rowbase + mf * 16 + lr) * PITCH + ks * 8 + lc;
                a[mf][0] = As[base];
                a[mf][1] = As[base + 8 * PITCH];
                a[mf][2] = As[base + 4];
                a[mf][3] = As[base + 8 * PITCH + 4];
            }
            #pragma unroll
            for (int nf = 0; nf < NF; nf++) {
                uint2 b = Wu[(ks * NFT + nhalf * NF + nf) * 32 + lane];
                #pragma unroll
                for (int mf = 0; mf < 2; mf++)
                    mma_tf32(acc[mf][nf], a[mf][0], a[mf][1], a[mf][2], a[mf][3], b.x, b.y);
            }
        }
    }
    // epilogue
    #pragma unroll
    for (int mf = 0; mf < 2; mf++) {
        int row0 = n0 + rowbase + mf * 16 + lr;
        #pragma unroll
        for (int nf = 0; nf < NF; nf++) {
            int col = nhalf * NPW + nf * 8 + lc * 2;
            float2 lo = make_float2(acc[mf][nf][0], acc[mf][nf][1]);
            float2 hi = make_float2(acc[mf][nf][2], acc[mf][nf][3]);
            *reinterpret_cast<float2*>(out + (size_t)row0 * COUT + col) = lo;
            *reinterpret_cast<float2*>(out + (size_t)(row0 + 8) * COUT + col) = hi;
        }
    }
}

// ---------------- decoder: [N,32] @ [32,96] -> [N,96], BM=64, 384 thr ----------
__global__ __launch_bounds__(384) void dec_kernel(const float* __restrict__ A,
                                                  const float* __restrict__ W,
                                                  float* __restrict__ C_, int N) {
    constexpr int K = 32, COUT = 96, BM = 64, PITCH = BM + 1;
    constexpr int TX = COUT / 4;  // 24
    __shared__ float As[K][PITCH];
    __shared__ __align__(16) float Bs[K][COUT];
    const int tid = threadIdx.x;
    const int tx = tid % TX;
    const int ty = tid / TX;
    const int n0 = blockIdx.x * BM;

    {
        const float4* W4 = reinterpret_cast<const float4*>(W);
        float4* bs4 = reinterpret_cast<float4*>(&Bs[0][0]);
        #pragma unroll
        for (int t = tid; t < K * COUT / 4; t += 384) bs4[t] = W4[t];
    }
    #pragma unroll
    for (int i = tid; i < BM * (K / 4); i += 384) {
        int r = i & (BM - 1), c4 = i / BM;
        float4 v = *reinterpret_cast<const float4*>(A + (size_t)(n0 + r) * K + c4 * 4);
        As[c4 * 4 + 0][r] = v.x;
        As[c4 * 4 + 1][r] = v.y;
        As[c4 * 4 + 2][r] = v.z;
        As[c4 * 4 + 3][r] = v.w;
    }
    __syncthreads();

    float acc[4][4] = {};
    #pragma unroll 8
    for (int kk = 0; kk < K; kk++) {
        float a[4], b[4];
        #pragma unroll
        for (int i = 0; i < 4; i++) a[i] = As[kk][ty * 4 + i];
        float4 bv = *reinterpret_cast<const float4*>(&Bs[kk][tx * 4]);
        b[0] = bv.x; b[1] = bv.y; b[2] = bv.z; b[3] = bv.w;
        #pragma unroll
        for (int i = 0; i < 4; i++)
            #pragma unroll
            for (int j = 0; j < 4; j++) acc[i][j] = fmaf(a[i], b[j], acc[i][j]);
    }
    #pragma unroll
    for (int i = 0; i < 4; i++) {
        int n = n0 + ty * 4 + i;
        float4 o = make_float4(acc[i][0], acc[i][1], acc[i][2], acc[i][3]);
        *reinterpret_cast<float4*>(C_ + (size_t)n * COUT + tx * 4) = o;
    }
}

// ---------------- host driver ----------------
static inline void run_stats(const float* X, int N, int C,
                             const float* g, const float* b,
                             float* part, float* ab, cudaStream_t st) {
    int C4 = C / 4;
    int TY = 256 / C4;
    dim3 blk(C4, TY);
    size_t sm = (size_t)2 * C * TY * sizeof(float);
    stats4_kernel<<<NBLK_STATS, blk, sm, st>>>(X, N, C, part);
    finalize_kernel<<<1, C, 0, st>>>(part, NBLK_STATS, C, 1.0f / (float)N, g, b, ab);
}

extern "C" void kernel_launch(void* const* d_in, const int* in_sizes, int n_in,
                              void* d_out, int out_size) {
    const float* x     = (const float*)d_in[0];
    const float* w_tr1 = (const float*)d_in[1];
    const float* g1    = (const float*)d_in[2];
    const float* b1    = (const float*)d_in[3];
    const int*   idx1  = (const int*)  d_in[4];
    const float* mask1 = (const float*)d_in[5];
    const float* w_c1  = (const float*)d_in[6];
    const float* g2    = (const float*)d_in[7];
    const float* b2    = (const float*)d_in[8];
    const float* w_tr2 = (const float*)d_in[9];
    const float* g3    = (const float*)d_in[10];
    const float* b3    = (const float*)d_in[11];
    const int*   idx2  = (const int*)  d_in[12];
    const float* mask2 = (const float*)d_in[13];
    const float* w_c2  = (const float*)d_in[14];
    const float* g4    = (const float*)d_in[15];
    const float* b4    = (const float*)d_in[16];
    const float* w_dec = (const float*)d_in[17];
    const float* g5    = (const float*)d_in[18];
    const float* b5    = (const float*)d_in[19];
    float* out = (float*)d_out;

    float *t1, *t2, *t3, *t4, *w2a, *w2b, *wf1, *wf2, *part, *ab;
    cudaGetSymbolAddress((void**)&t1, g_t1);
    cudaGetSymbolAddress((void**)&t2, g_t2);
    cudaGetSymbolAddress((void**)&t3, g_t3);
    cudaGetSymbolAddress((void**)&t4, g_t4);
    cudaGetSymbolAddress((void**)&w2a, g_w2a);
    cudaGetSymbolAddress((void**)&w2b, g_w2b);
    cudaGetSymbolAddress((void**)&wf1, g_wf1);
    cudaGetSymbolAddress((void**)&wf2, g_wf2);
    cudaGetSymbolAddress((void**)&part, g_part);
    cudaGetSymbolAddress((void**)&ab, g_ab);

    cudaStream_t st = 0;

    // smem opt-in for the mma conv kernels (idempotent, host-side, capture-safe)
    const int SMEM1 = 128 * (96 + 4) * 4 + 96 * 64 * 4 + 128 * 8;   // 77,824
    const int SMEM2 = 256 * (64 + 4) * 4 + 64 * 32 * 4 + 256 * 8;   // 79,872
    cudaFuncSetAttribute(conv3mma_kernel<96, 64, 128, 2>,
                         cudaFuncAttributeMaxDynamicSharedMemorySize, SMEM1);
    cudaFuncSetAttribute(conv3mma_kernel<64, 32, 256, 1>,
                         cudaFuncAttributeMaxDynamicSharedMemorySize, SMEM2);

    // 0) weight prep
    permute_w_kernel<<<(8 * 128 * 96 + 255) / 256, 256, 0, st>>>(w_tr1, w2a, 8, 128, 96);
    permute_w_kernel<<<(8 * 64 * 64 + 255) / 256, 256, 0, st>>>(w_tr2, w2b, 8, 64, 64);
    wfrag_kernel<<<(27 * 12 * 8 * 32 + 255) / 256, 256, 0, st>>>(w_c1, wf1, 96, 64);
    wfrag_kernel<<<(27 * 8 * 4 * 32 + 255) / 256, 256, 0, st>>>(w_c2, wf2, 64, 32);

    // 1) convtr2_1: [8000,128]@[128,768] -> t1 viewed [64000,96]
    {
        dim3 grid(768 / GBN, (N0 + GBM - 1) / GBM);
        gemm_kernel<<<grid, 256, 0, st>>>(x, w2a, t1, N0, 768, 128);
    }
    run_stats(t1, N1, 96, g1, b1, part, ab, st);
    bnrelu4_kernel<<<(N1 * 96 / 4 + 255) / 256, 256, 0, st>>>(t1, ab, N1 * 96 / 4, 96);

    // 2) conv3_1: [64000,96] -> [64000,64]  (tf32 mma, BM=128)
    conv3mma_kernel<96, 64, 128, 2><<<N1 / 128, 256, SMEM1, st>>>(t1, idx1, mask1, wf1, t2, N1);
    run_stats(t2, N1, 64, g2, b2, part, ab, st);
    bnrelu4_kernel<<<(N1 * 64 / 4 + 255) / 256, 256, 0, st>>>(t2, ab, N1 * 64 / 4, 64);

    // 3) convtr2_2: [64000,64]@[64,512] -> t3 viewed [512000,64]
    {
        dim3 grid(512 / GBN, N1 / GBM);
        gemm_kernel<<<grid, 256, 0, st>>>(t2, w2b, t3, N1, 512, 64);
    }
    run_stats(t3, N2, 64, g3, b3, part, ab, st);
    bnrelu4_kernel<<<(N2 * 64 / 4 + 255) / 256, 256, 0, st>>>(t3, ab, N2 * 64 / 4, 64);

    // 4) conv3_2: [512000,64] -> [512000,32]  (tf32 mma, BM=256)
    conv3mma_kernel<64, 32, 256, 1><<<N2 / 256, 256, SMEM2, st>>>(t3, idx2, mask2, wf2, t4, N2);
    run_stats(t4, N2, 32, g4, b4, part, ab, st);
    bnrelu_rowmean32_kernel<<<(N2 + 7) / 8, 256, 0, st>>>(t4, ab, out, N2);

    // 5) decoder: [512000,32]@[32,96] -> out+512000 (pre-BN), then BN+ReLU in place
    float* seg = out + N2;
    dec_kernel<<<N2 / 64, 384, 0, st>>>(t4, w_dec, seg, N2);
    run_stats(seg, N2, 96, g5, b5, part, ab, st);
    bnrelu4_kernel<<<(N2 * 96 / 4 + 255) / 256, 256, 0, st>>>(seg, ab, N2 * 96 / 4, 96);
}

// round 8
// speedup vs baseline: 1.0128x; 1.0128x over previous
#include <cuda_runtime.h>
#include <cuda_bf16.h>
#include <cstdint>

// ---------------- constants ----------------
#define N0 8000
#define N1 64000
#define N2 512000
#define NBLK_STATS 512

// ---------------- device scratch (no allocations allowed) ----------------
__device__ float g_t1[N1 * 96];        // layer1 out  [64000, 96]
__device__ float g_t2[N1 * 64];        // layer2 out  [64000, 64]
__device__ float g_t3[N2 * 64];        // layer3 out  [512000, 64]
__device__ float g_t4[N2 * 32];        // layer4 out  [512000, 32]
__device__ float g_w2a[128 * 8 * 96];  // permuted w_tr1 -> [128, 768]
__device__ float g_w2b[64 * 8 * 64];   // permuted w_tr2 -> [64, 512]
__device__ float g_wf1[27 * 96 * 64];  // w_c1 in tf32 fragment order
__device__ float g_wf2[27 * 64 * 32];  // w_c2 in tf32 fragment order
__device__ float g_part[NBLK_STATS * 2 * 96];
__device__ float g_ab[2 * 96];         // folded BN scale/shift

// ---------------- helpers ----------------
__device__ __forceinline__ uint32_t f2tf32(float f) {
    uint32_t u;
    asm("cvt.rna.tf32.f32 %0, %1;" : "=r"(u) : "f"(f));
    return u;
}

__device__ __forceinline__ void mma_tf32(float c[4], uint32_t a0, uint32_t a1,
                                         uint32_t a2, uint32_t a3,
                                         uint32_t b0, uint32_t b1) {
    asm("mma.sync.aligned.m16n8k8.row.col.f32.tf32.tf32.f32 "
        "{%0,%1,%2,%3},{%4,%5,%6,%7},{%8,%9},{%0,%1,%2,%3};"
        : "+f"(c[0]), "+f"(c[1]), "+f"(c[2]), "+f"(c[3])
        : "r"(a0), "r"(a1), "r"(a2), "r"(a3), "r"(b0), "r"(b1));
}

// ---------------- weight permute: w[k,c,d] -> W2[c, k*D+d] ----------------
__global__ void permute_w_kernel(const float* __restrict__ w, float* __restrict__ W2,
                                 int KK, int Cin, int D) {
    int t = blockIdx.x * blockDim.x + threadIdx.x;
    int tot = KK * Cin * D;
    if (t >= tot) return;
    int d = t % D;
    int c = (t / D) % Cin;
    int k = t / (D * Cin);
    W2[c * (KK * D) + k * D + d] = w[t];
}

// ---------------- wfrag prep: w[27,CIN,COUT] -> tf32 fragment order -------------
// wf[((k*KS + kk)*NFT + nf)*64 + lane*2 + {0,1}]
//   b0 = w[k][kk*8 + lane%4    ][nf*8 + lane/4]
//   b1 = w[k][kk*8 + lane%4 + 4][nf*8 + lane/4]
__global__ void wfrag_kernel(const float* __restrict__ w, float* __restrict__ wf,
                             int CIN, int COUT) {
    int t = blockIdx.x * blockDim.x + threadIdx.x;
    int KS = CIN / 8, NFT = COUT / 8;
    int tot = 27 * KS * NFT * 32;
    if (t >= tot) return;
    int lane = t & 31;
    int rest = t >> 5;
    int nf = rest % NFT; rest /= NFT;
    int kk = rest % KS;
    int k = rest / KS;
    int row = kk * 8 + (lane & 3);
    int col = nf * 8 + (lane >> 2);
    const float* wk = w + (size_t)k * CIN * COUT;
    wf[2 * t + 0] = __uint_as_float(f2tf32(wk[(size_t)row * COUT + col]));
    wf[2 * t + 1] = __uint_as_float(f2tf32(wk[(size_t)(row + 4) * COUT + col]));
}

// ---------------- fp32 tiled GEMM: C[M,N] = A[M,K] @ B[K,N] ----------------
#define GBM 64
#define GBN 64
#define GBK 16
#define GPITCH 68
__global__ __launch_bounds__(256) void gemm_kernel(const float* __restrict__ A,
                                                   const float* __restrict__ B,
                                                   float* __restrict__ C,
                                                   int M, int N, int K) {
    __shared__ __align__(16) float As[GBK][GPITCH];
    __shared__ __align__(16) float Bs[GBK][GBN];
    const int tid = threadIdx.x;
    const int tx = tid % 16;
    const int ty = tid / 16;
    const int rowBase = blockIdx.y * GBM;
    const int colBase = blockIdx.x * GBN;
    float acc[4][4] = {};
    for (int k0 = 0; k0 < K; k0 += GBK) {
        #pragma unroll
        for (int t = tid; t < GBM * GBK; t += 256) {
            int c = t % GBK, r = t / GBK;
            int gr = rowBase + r, gc = k0 + c;
            As[c][r] = (gr < M && gc < K) ? A[(size_t)gr * K + gc] : 0.f;
        }
        #pragma unroll
        for (int t = tid; t < GBK * GBN; t += 256) {
            int c = t % GBN, r = t / GBN;
            int gr = k0 + r, gc = colBase + c;
            Bs[r][c] = (gr < K && gc < N) ? B[(size_t)gr * N + gc] : 0.f;
        }
        __syncthreads();
        #pragma unroll
        for (int kk = 0; kk < GBK; kk++) {
            float4 av = *reinterpret_cast<const float4*>(&As[kk][ty * 4]);
            float4 bv = *reinterpret_cast<const float4*>(&Bs[kk][tx * 4]);
            float a[4] = {av.x, av.y, av.z, av.w};
            float b[4] = {bv.x, bv.y, bv.z, bv.w};
            #pragma unroll
            for (int i = 0; i < 4; i++)
                #pragma unroll
                for (int j = 0; j < 4; j++) acc[i][j] = fmaf(a[i], b[j], acc[i][j]);
        }
        __syncthreads();
    }
    #pragma unroll
    for (int i = 0; i < 4; i++) {
        int gr = rowBase + ty * 4 + i;
        if (gr >= M) continue;
        #pragma unroll
        for (int j = 0; j < 4; j++) {
            int gc = colBase + tx * 4 + j;
            if (gc < N) C[(size_t)gr * N + gc] = acc[i][j];
        }
    }
}

// ---------------- BN stats: per-block column sum/sumsq, float4, deterministic ------
__global__ void stats4_kernel(const float* __restrict__ X, int nrows, int C,
                              float* __restrict__ part) {
    extern __shared__ float sm[];
    const int C4 = C >> 2;
    const int c4 = threadIdx.x;
    const int ty = threadIdx.y;
    const int TY = blockDim.y;
    const float4* X4 = reinterpret_cast<const float4*>(X);
    float s0 = 0.f, s1 = 0.f, s2 = 0.f, s3 = 0.f;
    float q0 = 0.f, q1 = 0.f, q2 = 0.f, q3 = 0.f;
    for (int n = blockIdx.x * TY + ty; n < nrows; n += gridDim.x * TY) {
        float4 v = X4[(size_t)n * C4 + c4];
        s0 += v.x; q0 = fmaf(v.x, v.x, q0);
        s1 += v.y; q1 = fmaf(v.y, v.y, q1);
        s2 += v.z; q2 = fmaf(v.z, v.z, q2);
        s3 += v.w; q3 = fmaf(v.w, v.w, q3);
    }
    float* S = sm;
    float* Q = sm + TY * C;
    int cb = c4 * 4;
    S[ty * C + cb + 0] = s0; S[ty * C + cb + 1] = s1;
    S[ty * C + cb + 2] = s2; S[ty * C + cb + 3] = s3;
    Q[ty * C + cb + 0] = q0; Q[ty * C + cb + 1] = q1;
    Q[ty * C + cb + 2] = q2; Q[ty * C + cb + 3] = q3;
    __syncthreads();
    int tid = ty * C4 + c4;
    if (tid < C) {
        float s = 0.f, q = 0.f;
        for (int t = 0; t < TY; t++) { s += S[t * C + tid]; q += Q[t * C + tid]; }
        part[blockIdx.x * 2 * C + tid] = s;
        part[blockIdx.x * 2 * C + C + tid] = q;
    }
}

// ---------------- finalize: fold BN into a[c], b'[c] ----------------
__global__ void finalize_kernel(const float* __restrict__ part, int nblk, int C,
                                float invN, const float* __restrict__ g,
                                const float* __restrict__ b, float* __restrict__ ab) {
    int c = threadIdx.x;
    if (c >= C) return;
    float s = 0.f, q = 0.f;
    #pragma unroll 8
    for (int i = 0; i < nblk; i++) {
        s += part[i * 2 * C + c];
        q += part[i * 2 * C + C + c];
    }
    float mean = s * invN;
    float var = q * invN - mean * mean;
    float rstd = rsqrtf(var + 1e-5f);
    float a = g[c] * rstd;
    ab[c] = a;
    ab[C + c] = b[c] - mean * a;
}

// ---------------- BN apply + ReLU (in place, float4) ----------------
__global__ void bnrelu4_kernel(float* __restrict__ X, const float* __restrict__ ab,
                               int total4, int C) {
    int t = blockIdx.x * blockDim.x + threadIdx.x;
    if (t >= total4) return;
    int C4 = C >> 2;
    int c = (t % C4) * 4;
    float4 v = reinterpret_cast<float4*>(X)[t];
    v.x = fmaxf(fmaf(v.x, __ldg(ab + c + 0), __ldg(ab + C + c + 0)), 0.f);
    v.y = fmaxf(fmaf(v.y, __ldg(ab + c + 1), __ldg(ab + C + c + 1)), 0.f);
    v.z = fmaxf(fmaf(v.z, __ldg(ab + c + 2), __ldg(ab + C + c + 2)), 0.f);
    v.w = fmaxf(fmaf(v.w, __ldg(ab + c + 3), __ldg(ab + C + c + 3)), 0.f);
    reinterpret_cast<float4*>(X)[t] = v;
}

// ---------------- BN apply + ReLU + row-mean (layer 4, C=32) ----------------
__global__ void bnrelu_rowmean32_kernel(float* __restrict__ X, const float* __restrict__ ab,
                                        float* __restrict__ intensity, int N) {
    int gw = (blockIdx.x * blockDim.x + threadIdx.x) >> 5;
    int lane = threadIdx.x & 31;
    if (gw >= N) return;
    float v = fmaxf(fmaf(X[(size_t)gw * 32 + lane], ab[lane], ab[32 + lane]), 0.f);
    X[(size_t)gw * 32 + lane] = v;
    float s = v;
    #pragma unroll
    for (int o = 16; o; o >>= 1) s += __shfl_xor_sync(0xFFFFFFFFu, s, o);
    if (lane == 0) intensity[gw] = s * (1.f / 32.f);
}

// ---------------- conv3 via tf32 mma.sync gather-GEMM ----------------------
// Block: BM rows. 8 warps, each computes a 32 x (COUT/NWARP) tile.
// Per offset k: gather BM rows (mask-scaled, tf32-rounded) into SMEM As
// [BM][CIN+4], stage pre-fragmented W[k] slice, run m16n8k8 MMAs.
template <int CIN, int COUT, int BM, int NWARP>
__global__ __launch_bounds__(256) void conv3mma_kernel(
    const float* __restrict__ X, const int* __restrict__ idx,
    const float* __restrict__ mask, const float* __restrict__ Wf,
    float* __restrict__ out, int N) {
    constexpr int PITCH = CIN + 4;
    constexpr int C4 = CIN / 4;
    constexpr int KS = CIN / 8;
    constexpr int NFT = COUT / 8;
    constexpr int NPW = COUT / NWARP;   // cols per warp
    constexpr int NF = NPW / 8;         // n-frags per warp
    constexpr int ROWTILES = BM / 32;
    static_assert(ROWTILES * NWARP == 8, "need 8 warps");

    extern __shared__ __align__(16) char smem_raw[];
    uint32_t* As = reinterpret_cast<uint32_t*>(smem_raw);            // BM*PITCH
    float* Wfs = reinterpret_cast<float*>(As + BM * PITCH);          // CIN*COUT
    int* ridx = reinterpret_cast<int*>(Wfs + CIN * COUT);            // BM
    float* rmask = reinterpret_cast<float*>(ridx + BM);              // BM

    const int tid = threadIdx.x;
    const int w = tid >> 5;
    const int lane = tid & 31;
    const int lr = lane >> 2;   // groupID
    const int lc = lane & 3;    // thread in group
    const int rowtile = w / NWARP;
    const int nhalf = w % NWARP;
    const int rowbase = rowtile * 32;
    const int n0 = blockIdx.x * BM;
    const float4* X4 = reinterpret_cast<const float4*>(X);

    float acc[2][NF][4];
    #pragma unroll
    for (int mf = 0; mf < 2; mf++)
        #pragma unroll
        for (int nf = 0; nf < NF; nf++)
            #pragma unroll
            for (int i = 0; i < 4; i++) acc[mf][nf][i] = 0.f;

    for (int k = 0; k < 27; k++) {
        __syncthreads();  // previous compute done; As/Wfs/ridx reusable
        if (tid < BM) {
            int n = n0 + tid;
            ridx[tid] = idx[(size_t)k * N + n];
            rmask[tid] = mask[(size_t)k * N + n];
        }
        {
            const float4* src = reinterpret_cast<const float4*>(Wf + (size_t)k * CIN * COUT);
            float4* dst = reinterpret_cast<float4*>(Wfs);
            #pragma unroll
            for (int t = tid; t < CIN * COUT / 4; t += 256) dst[t] = src[t];
        }
        __syncthreads();  // ridx/rmask visible
        // gather + mask + tf32 round
        #pragma unroll
        for (int t = tid; t < BM * C4; t += 256) {
            int r = t / C4, c4 = t % C4;
            float4 v = X4[(size_t)ridx[r] * C4 + c4];
            float m = rmask[r];
            uint4 u;
            u.x = f2tf32(v.x * m);
            u.y = f2tf32(v.y * m);
            u.z = f2tf32(v.z * m);
            u.w = f2tf32(v.w * m);
            *reinterpret_cast<uint4*>(As + r * PITCH + c4 * 4) = u;
        }
        __syncthreads();  // As visible
        // MMA over K
        const uint2* Wu = reinterpret_cast<const uint2*>(Wfs);
        #pragma unroll
        for (int ks = 0; ks < KS; ks++) {
            uint32_t a[2][4];
            #pragma unroll
            for (int mf = 0; mf < 2; mf++) {
                int base = (rowbase + mf * 16 + lr) * PITCH + ks * 8 + lc;
                a[mf][0] = As[base];
                a[mf][1] = As[base + 8 * PITCH];
                a[mf][2] = As[base + 4];
                a[mf][3] = As[base + 8 * PITCH + 4];
            }
            #pragma unroll
            for (int nf = 0; nf < NF; nf++) {
                uint2 b = Wu[(ks * NFT + nhalf * NF + nf) * 32 + lane];
                #pragma unroll
                for (int mf = 0; mf < 2; mf++)
                    mma_tf32(acc[mf][nf], a[mf][0], a[mf][1], a[mf][2], a[mf][3], b.x, b.y);
            }
        }
    }
    // epilogue
    #pragma unroll
    for (int mf = 0; mf < 2; mf++) {
        int row0 = n0 + rowbase + mf * 16 + lr;
        #pragma unroll
        for (int nf = 0; nf < NF; nf++) {
            int col = nhalf * NPW + nf * 8 + lc * 2;
            float2 lo = make_float2(acc[mf][nf][0], acc[mf][nf][1]);
            float2 hi = make_float2(acc[mf][nf][2], acc[mf][nf][3]);
            *reinterpret_cast<float2*>(out + (size_t)row0 * COUT + col) = lo;
            *reinterpret_cast<float2*>(out + (size_t)(row0 + 8) * COUT + col) = hi;
        }
    }
}

// ---------------- decoder: [N,32] @ [32,96] -> [N,96], BM=64, 384 thr ----------
__global__ __launch_bounds__(384) void dec_kernel(const float* __restrict__ A,
                                                  const float* __restrict__ W,
                                                  float* __restrict__ C_, int N) {
    constexpr int K = 32, COUT = 96, BM = 64, PITCH = BM + 1;
    constexpr int TX = COUT / 4;  // 24
    __shared__ float As[K][PITCH];
    __shared__ __align__(16) float Bs[K][COUT];
    const int tid = threadIdx.x;
    const int tx = tid % TX;
    const int ty = tid / TX;
    const int n0 = blockIdx.x * BM;

    {
        const float4* W4 = reinterpret_cast<const float4*>(W);
        float4* bs4 = reinterpret_cast<float4*>(&Bs[0][0]);
        #pragma unroll
        for (int t = tid; t < K * COUT / 4; t += 384) bs4[t] = W4[t];
    }
    #pragma unroll
    for (int i = tid; i < BM * (K / 4); i += 384) {
        int r = i & (BM - 1), c4 = i / BM;
        float4 v = *reinterpret_cast<const float4*>(A + (size_t)(n0 + r) * K + c4 * 4);
        As[c4 * 4 + 0][r] = v.x;
        As[c4 * 4 + 1][r] = v.y;
        As[c4 * 4 + 2][r] = v.z;
        As[c4 * 4 + 3][r] = v.w;
    }
    __syncthreads();

    float acc[4][4] = {};
    #pragma unroll 8
    for (int kk = 0; kk < K; kk++) {
        float a[4], b[4];
        #pragma unroll
        for (int i = 0; i < 4; i++) a[i] = As[kk][ty * 4 + i];
        float4 bv = *reinterpret_cast<const float4*>(&Bs[kk][tx * 4]);
        b[0] = bv.x; b[1] = bv.y; b[2] = bv.z; b[3] = bv.w;
        #pragma unroll
        for (int i = 0; i < 4; i++)
            #pragma unroll
            for (int j = 0; j < 4; j++) acc[i][j] = fmaf(a[i], b[j], acc[i][j]);
    }
    #pragma unroll
    for (int i = 0; i < 4; i++) {
        int n = n0 + ty * 4 + i;
        float4 o = make_float4(acc[i][0], acc[i][1], acc[i][2], acc[i][3]);
        *reinterpret_cast<float4*>(C_ + (size_t)n * COUT + tx * 4) = o;
    }
}

// ---------------- host driver ----------------
static inline void run_stats(const float* X, int N, int C,
                             const float* g, const float* b,
                             float* part, float* ab, cudaStream_t st) {
    int C4 = C / 4;
    int TY = 256 / C4;
    dim3 blk(C4, TY);
    size_t sm = (size_t)2 * C * TY * sizeof(float);
    stats4_kernel<<<NBLK_STATS, blk, sm, st>>>(X, N, C, part);
    finalize_kernel<<<1, C, 0, st>>>(part, NBLK_STATS, C, 1.0f / (float)N, g, b, ab);
}

extern "C" void kernel_launch(void* const* d_in, const int* in_sizes, int n_in,
                              void* d_out, int out_size) {
    const float* x     = (const float*)d_in[0];
    const float* w_tr1 = (const float*)d_in[1];
    const float* g1    = (const float*)d_in[2];
    const float* b1    = (const float*)d_in[3];
    const int*   idx1  = (const int*)  d_in[4];
    const float* mask1 = (const float*)d_in[5];
    const float* w_c1  = (const float*)d_in[6];
    const float* g2    = (const float*)d_in[7];
    const float* b2    = (const float*)d_in[8];
    const float* w_tr2 = (const float*)d_in[9];
    const float* g3    = (const float*)d_in[10];
    const float* b3    = (const float*)d_in[11];
    const int*   idx2  = (const int*)  d_in[12];
    const float* mask2 = (const float*)d_in[13];
    const float* w_c2  = (const float*)d_in[14];
    const float* g4    = (const float*)d_in[15];
    const float* b4    = (const float*)d_in[16];
    const float* w_dec = (const float*)d_in[17];
    const float* g5    = (const float*)d_in[18];
    const float* b5    = (const float*)d_in[19];
    float* out = (float*)d_out;

    float *t1, *t2, *t3, *t4, *w2a, *w2b, *wf1, *wf2, *part, *ab;
    cudaGetSymbolAddress((void**)&t1, g_t1);
    cudaGetSymbolAddress((void**)&t2, g_t2);
    cudaGetSymbolAddress((void**)&t3, g_t3);
    cudaGetSymbolAddress((void**)&t4, g_t4);
    cudaGetSymbolAddress((void**)&w2a, g_w2a);
    cudaGetSymbolAddress((void**)&w2b, g_w2b);
    cudaGetSymbolAddress((void**)&wf1, g_wf1);
    cudaGetSymbolAddress((void**)&wf2, g_wf2);
    cudaGetSymbolAddress((void**)&part, g_part);
    cudaGetSymbolAddress((void**)&ab, g_ab);

    cudaStream_t st = 0;

    // smem opt-in for the mma conv kernels (idempotent, host-side, capture-safe)
    const int SMEM1 = 128 * (96 + 4) * 4 + 96 * 64 * 4 + 128 * 8;   // 77,824
    const int SMEM2 = 256 * (64 + 4) * 4 + 64 * 32 * 4 + 256 * 8;   // 79,872
    cudaFuncSetAttribute(conv3mma_kernel<96, 64, 128, 2>,
                         cudaFuncAttributeMaxDynamicSharedMemorySize, SMEM1);
    cudaFuncSetAttribute(conv3mma_kernel<64, 32, 256, 1>,
                         cudaFuncAttributeMaxDynamicSharedMemorySize, SMEM2);

    // 0) weight prep
    permute_w_kernel<<<(8 * 128 * 96 + 255) / 256, 256, 0, st>>>(w_tr1, w2a, 8, 128, 96);
    permute_w_kernel<<<(8 * 64 * 64 + 255) / 256, 256, 0, st>>>(w_tr2, w2b, 8, 64, 64);
    wfrag_kernel<<<(27 * 12 * 8 * 32 + 255) / 256, 256, 0, st>>>(w_c1, wf1, 96, 64);
    wfrag_kernel<<<(27 * 8 * 4 * 32 + 255) / 256, 256, 0, st>>>(w_c2, wf2, 64, 32);

    // 1) convtr2_1: [8000,128]@[128,768] -> t1 viewed [64000,96]
    {
        dim3 grid(768 / GBN, (N0 + GBM - 1) / GBM);
        gemm_kernel<<<grid, 256, 0, st>>>(x, w2a, t1, N0, 768, 128);
    }
    run_stats(t1, N1, 96, g1, b1, part, ab, st);
    bnrelu4_kernel<<<(N1 * 96 / 4 + 255) / 256, 256, 0, st>>>(t1, ab, N1 * 96 / 4, 96);

    // 2) conv3_1: [64000,96] -> [64000,64]  (tf32 mma, BM=128)
    conv3mma_kernel<96, 64, 128, 2><<<N1 / 128, 256, SMEM1, st>>>(t1, idx1, mask1, wf1, t2, N1);
    run_stats(t2, N1, 64, g2, b2, part, ab, st);
    bnrelu4_kernel<<<(N1 * 64 / 4 + 255) / 256, 256, 0, st>>>(t2, ab, N1 * 64 / 4, 64);

    // 3) convtr2_2: [64000,64]@[64,512] -> t3 viewed [512000,64]
    {
        dim3 grid(512 / GBN, N1 / GBM);
        gemm_kernel<<<grid, 256, 0, st>>>(t2, w2b, t3, N1, 512, 64);
    }
    run_stats(t3, N2, 64, g3, b3, part, ab, st);
    bnrelu4_kernel<<<(N2 * 64 / 4 + 255) / 256, 256, 0, st>>>(t3, ab, N2 * 64 / 4, 64);

    // 4) conv3_2: [512000,64] -> [512000,32]  (tf32 mma, BM=256)
    conv3mma_kernel<64, 32, 256, 1><<<N2 / 256, 256, SMEM2, st>>>(t3, idx2, mask2, wf2, t4, N2);
    run_stats(t4, N2, 32, g4, b4, part, ab, st);
    bnrelu_rowmean32_kernel<<<(N2 + 7) / 8, 256, 0, st>>>(t4, ab, out, N2);

    // 5) decoder: [512000,32]@[32,96] -> out+512000 (pre-BN), then BN+ReLU in place
    float* seg = out + N2;
    dec_kernel<<<N2 / 64, 384, 0, st>>>(t4, w_dec, seg, N2);
    run_stats(seg, N2, 96, g5, b5, part, ab, st);
    bnrelu4_kernel<<<(N2 * 96 / 4 + 255) / 256, 256, 0, st>>>(seg, ab, N2 * 96 / 4, 96);
}

// round 9
// speedup vs baseline: 1.0135x; 1.0007x over previous
#include <cuda_runtime.h>
#include <cuda_bf16.h>
#include <cstdint>

// ---------------- constants ----------------
#define N0 8000
#define N1 64000
#define N2 512000
#define NBLK_STATS 512

// ---------------- device scratch (no allocations allowed) ----------------
__device__ float g_t1[N1 * 96];        // layer1 out  [64000, 96]
__device__ float g_t2[N1 * 64];        // layer2 out  [64000, 64]
__device__ float g_t3[N2 * 64];        // layer3 out  [512000, 64]
__device__ float g_t4[N2 * 32];        // layer4 out  [512000, 32]
__device__ float g_w2a[128 * 8 * 96];  // permuted w_tr1 -> [128, 768]
__device__ float g_w2b[64 * 8 * 64];   // permuted w_tr2 -> [64, 512]
__device__ float g_wf1[27 * 96 * 64];  // w_c1 in tf32 fragment order
__device__ float g_wf2[27 * 64 * 32];  // w_c2 in tf32 fragment order
__device__ float g_part[NBLK_STATS * 2 * 96];
__device__ float g_ab[2 * 96];         // folded BN scale/shift

// ---------------- helpers ----------------
__device__ __forceinline__ uint32_t f2tf32(float f) {
    uint32_t u;
    asm("cvt.rna.tf32.f32 %0, %1;" : "=r"(u) : "f"(f));
    return u;
}

__device__ __forceinline__ void mma_tf32(float c[4], uint32_t a0, uint32_t a1,
                                         uint32_t a2, uint32_t a3,
                                         uint32_t b0, uint32_t b1) {
    asm("mma.sync.aligned.m16n8k8.row.col.f32.tf32.tf32.f32 "
        "{%0,%1,%2,%3},{%4,%5,%6,%7},{%8,%9},{%0,%1,%2,%3};"
        : "+f"(c[0]), "+f"(c[1]), "+f"(c[2]), "+f"(c[3])
        : "r"(a0), "r"(a1), "r"(a2), "r"(a3), "r"(b0), "r"(b1));
}

// ---------------- weight permute: w[k,c,d] -> W2[c, k*D+d] ----------------
__global__ void permute_w_kernel(const float* __restrict__ w, float* __restrict__ W2,
                                 int KK, int Cin, int D) {
    int t = blockIdx.x * blockDim.x + threadIdx.x;
    int tot = KK * Cin * D;
    if (t >= tot) return;
    int d = t % D;
    int c = (t / D) % Cin;
    int k = t / (D * Cin);
    W2[c * (KK * D) + k * D + d] = w[t];
}

// ---------------- wfrag prep: w[27,CIN,COUT] -> tf32 fragment order -------------
// wf[((k*KS + kk)*NFT + nf)*64 + lane*2 + {0,1}]
//   b0 = w[k][kk*8 + lane%4    ][nf*8 + lane/4]
//   b1 = w[k][kk*8 + lane%4 + 4][nf*8 + lane/4]
__global__ void wfrag_kernel(const float* __restrict__ w, float* __restrict__ wf,
                             int CIN, int COUT) {
    int t = blockIdx.x * blockDim.x + threadIdx.x;
    int KS = CIN / 8, NFT = COUT / 8;
    int tot = 27 * KS * NFT * 32;
    if (t >= tot) return;
    int lane = t & 31;
    int rest = t >> 5;
    int nf = rest % NFT; rest /= NFT;
    int kk = rest % KS;
    int k = rest / KS;
    int row = kk * 8 + (lane & 3);
    int col = nf * 8 + (lane >> 2);
    const float* wk = w + (size_t)k * CIN * COUT;
    wf[2 * t + 0] = __uint_as_float(f2tf32(wk[(size_t)row * COUT + col]));
    wf[2 * t + 1] = __uint_as_float(f2tf32(wk[(size_t)(row + 4) * COUT + col]));
}

// ---------------- fp32 tiled GEMM: C[M,N] = A[M,K] @ B[K,N] ----------------
#define GBM 64
#define GBN 64
#define GBK 16
#define GPITCH 68
__global__ __launch_bounds__(256) void gemm_kernel(const float* __restrict__ A,
                                                   const float* __restrict__ B,
                                                   float* __restrict__ C,
                                                   int M, int N, int K) {
    __shared__ __align__(16) float As[GBK][GPITCH];
    __shared__ __align__(16) float Bs[GBK][GBN];
    const int tid = threadIdx.x;
    const int tx = tid % 16;
    const int ty = tid / 16;
    const int rowBase = blockIdx.y * GBM;
    const int colBase = blockIdx.x * GBN;
    float acc[4][4] = {};
    for (int k0 = 0; k0 < K; k0 += GBK) {
        #pragma unroll
        for (int t = tid; t < GBM * GBK; t += 256) {
            int c = t % GBK, r = t / GBK;
            int gr = rowBase + r, gc = k0 + c;
            As[c][r] = (gr < M && gc < K) ? A[(size_t)gr * K + gc] : 0.f;
        }
        #pragma unroll
        for (int t = tid; t < GBK * GBN; t += 256) {
            int c = t % GBN, r = t / GBN;
            int gr = k0 + r, gc = colBase + c;
            Bs[r][c] = (gr < K && gc < N) ? B[(size_t)gr * N + gc] : 0.f;
        }
        __syncthreads();
        #pragma unroll
        for (int kk = 0; kk < GBK; kk++) {
            float4 av = *reinterpret_cast<const float4*>(&As[kk][ty * 4]);
            float4 bv = *reinterpret_cast<const float4*>(&Bs[kk][tx * 4]);
            float a[4] = {av.x, av.y, av.z, av.w};
            float b[4] = {bv.x, bv.y, bv.z, bv.w};
            #pragma unroll
            for (int i = 0; i < 4; i++)
                #pragma unroll
                for (int j = 0; j < 4; j++) acc[i][j] = fmaf(a[i], b[j], acc[i][j]);
        }
        __syncthreads();
    }
    #pragma unroll
    for (int i = 0; i < 4; i++) {
        int gr = rowBase + ty * 4 + i;
        if (gr >= M) continue;
        #pragma unroll
        for (int j = 0; j < 4; j++) {
            int gc = colBase + tx * 4 + j;
            if (gc < N) C[(size_t)gr * N + gc] = acc[i][j];
        }
    }
}

// ---------------- BN stats: per-block column sum/sumsq, float4, deterministic ------
__global__ void stats4_kernel(const float* __restrict__ X, int nrows, int C,
                              float* __restrict__ part) {
    extern __shared__ float sm[];
    const int C4 = C >> 2;
    const int c4 = threadIdx.x;
    const int ty = threadIdx.y;
    const int TY = blockDim.y;
    const float4* X4 = reinterpret_cast<const float4*>(X);
    float s0 = 0.f, s1 = 0.f, s2 = 0.f, s3 = 0.f;
    float q0 = 0.f, q1 = 0.f, q2 = 0.f, q3 = 0.f;
    for (int n = blockIdx.x * TY + ty; n < nrows; n += gridDim.x * TY) {
        float4 v = X4[(size_t)n * C4 + c4];
        s0 += v.x; q0 = fmaf(v.x, v.x, q0);
        s1 += v.y; q1 = fmaf(v.y, v.y, q1);
        s2 += v.z; q2 = fmaf(v.z, v.z, q2);
        s3 += v.w; q3 = fmaf(v.w, v.w, q3);
    }
    float* S = sm;
    float* Q = sm + TY * C;
    int cb = c4 * 4;
    S[ty * C + cb + 0] = s0; S[ty * C + cb + 1] = s1;
    S[ty * C + cb + 2] = s2; S[ty * C + cb + 3] = s3;
    Q[ty * C + cb + 0] = q0; Q[ty * C + cb + 1] = q1;
    Q[ty * C + cb + 2] = q2; Q[ty * C + cb + 3] = q3;
    __syncthreads();
    int tid = ty * C4 + c4;
    if (tid < C) {
        float s = 0.f, q = 0.f;
        for (int t = 0; t < TY; t++) { s += S[t * C + tid]; q += Q[t * C + tid]; }
        part[blockIdx.x * 2 * C + tid] = s;
        part[blockIdx.x * 2 * C + C + tid] = q;
    }
}

// ---------------- finalize: fold BN into a[c], b'[c] ----------------
__global__ void finalize_kernel(const float* __restrict__ part, int nblk, int C,
                                float invN, const float* __restrict__ g,
                                const float* __restrict__ b, float* __restrict__ ab) {
    int c = threadIdx.x;
    if (c >= C) return;
    float s = 0.f, q = 0.f;
    #pragma unroll 8
    for (int i = 0; i < nblk; i++) {
        s += part[i * 2 * C + c];
        q += part[i * 2 * C + C + c];
    }
    float mean = s * invN;
    float var = q * invN - mean * mean;
    float rstd = rsqrtf(var + 1e-5f);
    float a = g[c] * rstd;
    ab[c] = a;
    ab[C + c] = b[c] - mean * a;
}

// ---------------- BN apply + ReLU (in place, float4) ----------------
__global__ void bnrelu4_kernel(float* __restrict__ X, const float* __restrict__ ab,
                               int total4, int C) {
    int t = blockIdx.x * blockDim.x + threadIdx.x;
    if (t >= total4) return;
    int C4 = C >> 2;
    int c = (t % C4) * 4;
    float4 v = reinterpret_cast<float4*>(X)[t];
    v.x = fmaxf(fmaf(v.x, __ldg(ab + c + 0), __ldg(ab + C + c + 0)), 0.f);
    v.y = fmaxf(fmaf(v.y, __ldg(ab + c + 1), __ldg(ab + C + c + 1)), 0.f);
    v.z = fmaxf(fmaf(v.z, __ldg(ab + c + 2), __ldg(ab + C + c + 2)), 0.f);
    v.w = fmaxf(fmaf(v.w, __ldg(ab + c + 3), __ldg(ab + C + c + 3)), 0.f);
    reinterpret_cast<float4*>(X)[t] = v;
}

// ---------------- BN apply + ReLU + row-mean (layer 4, C=32) ----------------
__global__ void bnrelu_rowmean32_kernel(float* __restrict__ X, const float* __restrict__ ab,
                                        float* __restrict__ intensity, int N) {
    int gw = (blockIdx.x * blockDim.x + threadIdx.x) >> 5;
    int lane = threadIdx.x & 31;
    if (gw >= N) return;
    float v = fmaxf(fmaf(X[(size_t)gw * 32 + lane], ab[lane], ab[32 + lane]), 0.f);
    X[(size_t)gw * 32 + lane] = v;
    float s = v;
    #pragma unroll
    for (int o = 16; o; o >>= 1) s += __shfl_xor_sync(0xFFFFFFFFu, s, o);
    if (lane == 0) intensity[gw] = s * (1.f / 32.f);
}

// ---------------- conv3 via tf32 mma.sync gather-GEMM ----------------------
// Block: BM rows. 8 warps, each computes a 32 x (COUT/NWARP) tile.
// Per offset k: gather BM rows (mask-scaled, tf32-rounded) into SMEM As
// [BM][CIN+4], stage pre-fragmented W[k] slice, run m16n8k8 MMAs.
template <int CIN, int COUT, int BM, int NWARP>
__global__ __launch_bounds__(256) void conv3mma_kernel(
    const float* __restrict__ X, const int* __restrict__ idx,
    const float* __restrict__ mask, const float* __restrict__ Wf,
    float* __restrict__ out, int N) {
    constexpr int PITCH = CIN + 4;
    constexpr int C4 = CIN / 4;
    constexpr int KS = CIN / 8;
    constexpr int NFT = COUT / 8;
    constexpr int NPW = COUT / NWARP;   // cols per warp
    constexpr int NF = NPW / 8;         // n-frags per warp
    constexpr int ROWTILES = BM / 32;
    static_assert(ROWTILES * NWARP == 8, "need 8 warps");

    extern __shared__ __align__(16) char smem_raw[];
    uint32_t* As = reinterpret_cast<uint32_t*>(smem_raw);            // BM*PITCH
    float* Wfs = reinterpret_cast<float*>(As + BM * PITCH);          // CIN*COUT
    int* ridx = reinterpret_cast<int*>(Wfs + CIN * COUT);            // BM
    float* rmask = reinterpret_cast<float*>(ridx + BM);              // BM

    const int tid = threadIdx.x;
    const int w = tid >> 5;
    const int lane = tid & 31;
    const int lr = lane >> 2;   // groupID
    const int lc = lane & 3;    // thread in group
    const int rowtile = w / NWARP;
    const int nhalf = w % NWARP;
    const int rowbase = rowtile * 32;
    const int n0 = blockIdx.x * BM;
    const float4* X4 = reinterpret_cast<const float4*>(X);

    float acc[2][NF][4];
    #pragma unroll
    for (int mf = 0; mf < 2; mf++)
        #pragma unroll
        for (int nf = 0; nf < NF; nf++)
            #pragma unroll
            for (int i = 0; i < 4; i++) acc[mf][nf][i] = 0.f;

    for (int k = 0; k < 27; k++) {
        __syncthreads();  // previous compute done; As/Wfs/ridx reusable
        if (tid < BM) {
            int n = n0 + tid;
            ridx[tid] = idx[(size_t)k * N + n];
            rmask[tid] = mask[(size_t)k * N + n];
        }
        {
            const float4* src = reinterpret_cast<const float4*>(Wf + (size_t)k * CIN * COUT);
            float4* dst = reinterpret_cast<float4*>(Wfs);
            #pragma unroll
            for (int t = tid; t < CIN * COUT / 4; t += 256) dst[t] = src[t];
        }
        __syncthreads();  // ridx/rmask visible
        // gather + mask + tf32 round
        #pragma unroll
        for (int t = tid; t < BM * C4; t += 256) {
            int r = t / C4, c4 = t % C4;
            float4 v = X4[(size_t)ridx[r] * C4 + c4];
            float m = rmask[r];
            uint4 u;
            u.x = f2tf32(v.x * m);
            u.y = f2tf32(v.y * m);
            u.z = f2tf32(v.z * m);
            u.w = f2tf32(v.w * m);
            *reinterpret_cast<uint4*>(As + r * PITCH + c4 * 4) = u;
        }
        __syncthreads();  // As visible
        // MMA over K
        const uint2* Wu = reinterpret_cast<const uint2*>(Wfs);
        #pragma unroll
        for (int ks = 0; ks < KS; ks++) {
            uint32_t a[2][4];
            #pragma unroll
            for (int mf = 0; mf < 2; mf++) {
                int base = (rowbase + mf * 16 + lr) * PITCH + ks * 8 + lc;
                a[mf][0] = As[base];
                a[mf][1] = As[base + 8 * PITCH];
                a[mf][2] = As[base + 4];
                a[mf][3] = As[base + 8 * PITCH + 4];
            }
            #pragma unroll
            for (int nf = 0; nf < NF; nf++) {
                uint2 b = Wu[(ks * NFT + nhalf * NF + nf) * 32 + lane];
                #pragma unroll
                for (int mf = 0; mf < 2; mf++)
                    mma_tf32(acc[mf][nf], a[mf][0], a[mf][1], a[mf][2], a[mf][3], b.x, b.y);
            }
        }
    }
    // epilogue
    #pragma unroll
    for (int mf = 0; mf < 2; mf++) {
        int row0 = n0 + rowbase + mf * 16 + lr;
        #pragma unroll
        for (int nf = 0; nf < NF; nf++) {
            int col = nhalf * NPW + nf * 8 + lc * 2;
            float2 lo = make_float2(acc[mf][nf][0], acc[mf][nf][1]);
            float2 hi = make_float2(acc[mf][nf][2], acc[mf][nf][3]);
            *reinterpret_cast<float2*>(out + (size_t)row0 * COUT + col) = lo;
            *reinterpret_cast<float2*>(out + (size_t)(row0 + 8) * COUT + col) = hi;
        }
    }
}

// ---------------- decoder: [N,32] @ [32,96] -> [N,96], BM=64, 384 thr ----------
__global__ __launch_bounds__(384) void dec_kernel(const float* __restrict__ A,
                                                  const float* __restrict__ W,
                                                  float* __restrict__ C_, int N) {
    constexpr int K = 32, COUT = 96, BM = 64, PITCH = BM + 1;
    constexpr int TX = COUT / 4;  // 24
    __shared__ float As[K][PITCH];
    __shared__ __align__(16) float Bs[K][COUT];
    const int tid = threadIdx.x;
    const int tx = tid % TX;
    const int ty = tid / TX;
    const int n0 = blockIdx.x * BM;

    {
        const float4* W4 = reinterpret_cast<const float4*>(W);
        float4* bs4 = reinterpret_cast<float4*>(&Bs[0][0]);
        #pragma unroll
        for (int t = tid; t < K * COUT / 4; t += 384) bs4[t] = W4[t];
    }
    #pragma unroll
    for (int i = tid; i < BM * (K / 4); i += 384) {
        int r = i & (BM - 1), c4 = i / BM;
        float4 v = *reinterpret_cast<const float4*>(A + (size_t)(n0 + r) * K + c4 * 4);
        As[c4 * 4 + 0][r] = v.x;
        As[c4 * 4 + 1][r] = v.y;
        As[c4 * 4 + 2][r] = v.z;
        As[c4 * 4 + 3][r] = v.w;
    }
    __syncthreads();

    float acc[4][4] = {};
    #pragma unroll 8
    for (int kk = 0; kk < K; kk++) {
        float a[4], b[4];
        #pragma unroll
        for (int i = 0; i < 4; i++) a[i] = As[kk][ty * 4 + i];
        float4 bv = *reinterpret_cast<const float4*>(&Bs[kk][tx * 4]);
        b[0] = bv.x; b[1] = bv.y; b[2] = bv.z; b[3] = bv.w;
        #pragma unroll
        for (int i = 0; i < 4; i++)
            #pragma unroll
            for (int j = 0; j < 4; j++) acc[i][j] = fmaf(a[i], b[j], acc[i][j]);
    }
    #pragma unroll
    for (int i = 0; i < 4; i++) {
        int n = n0 + ty * 4 + i;
        float4 o = make_float4(acc[i][0], acc[i][1], acc[i][2], acc[i][3]);
        *reinterpret_cast<float4*>(C_ + (size_t)n * COUT + tx * 4) = o;
    }
}

// ---------------- host driver ----------------
static inline void run_stats(const float* X, int N, int C,
                             const float* g, const float* b,
                             float* part, float* ab, cudaStream_t st) {
    int C4 = C / 4;
    int TY = 256 / C4;
    dim3 blk(C4, TY);
    size_t sm = (size_t)2 * C * TY * sizeof(float);
    stats4_kernel<<<NBLK_STATS, blk, sm, st>>>(X, N, C, part);
    finalize_kernel<<<1, C, 0, st>>>(part, NBLK_STATS, C, 1.0f / (float)N, g, b, ab);
}

extern "C" void kernel_launch(void* const* d_in, const int* in_sizes, int n_in,
                              void* d_out, int out_size) {
    const float* x     = (const float*)d_in[0];
    const float* w_tr1 = (const float*)d_in[1];
    const float* g1    = (const float*)d_in[2];
    const float* b1    = (const float*)d_in[3];
    const int*   idx1  = (const int*)  d_in[4];
    const float* mask1 = (const float*)d_in[5];
    const float* w_c1  = (const float*)d_in[6];
    const float* g2    = (const float*)d_in[7];
    const float* b2    = (const float*)d_in[8];
    const float* w_tr2 = (const float*)d_in[9];
    const float* g3    = (const float*)d_in[10];
    const float* b3    = (const float*)d_in[11];
    const int*   idx2  = (const int*)  d_in[12];
    const float* mask2 = (const float*)d_in[13];
    const float* w_c2  = (const float*)d_in[14];
    const float* g4    = (const float*)d_in[15];
    const float* b4    = (const float*)d_in[16];
    const float* w_dec = (const float*)d_in[17];
    const float* g5    = (const float*)d_in[18];
    const float* b5    = (const float*)d_in[19];
    float* out = (float*)d_out;

    float *t1, *t2, *t3, *t4, *w2a, *w2b, *wf1, *wf2, *part, *ab;
    cudaGetSymbolAddress((void**)&t1, g_t1);
    cudaGetSymbolAddress((void**)&t2, g_t2);
    cudaGetSymbolAddress((void**)&t3, g_t3);
    cudaGetSymbolAddress((void**)&t4, g_t4);
    cudaGetSymbolAddress((void**)&w2a, g_w2a);
    cudaGetSymbolAddress((void**)&w2b, g_w2b);
    cudaGetSymbolAddress((void**)&wf1, g_wf1);
    cudaGetSymbolAddress((void**)&wf2, g_wf2);
    cudaGetSymbolAddress((void**)&part, g_part);
    cudaGetSymbolAddress((void**)&ab, g_ab);

    cudaStream_t st = 0;

    // smem opt-in for the mma conv kernels (idempotent, host-side, capture-safe)
    const int SMEM1 = 128 * (96 + 4) * 4 + 96 * 64 * 4 + 128 * 8;   // 77,824
    const int SMEM2 = 256 * (64 + 4) * 4 + 64 * 32 * 4 + 256 * 8;   // 79,872
    cudaFuncSetAttribute(conv3mma_kernel<96, 64, 128, 2>,
                         cudaFuncAttributeMaxDynamicSharedMemorySize, SMEM1);
    cudaFuncSetAttribute(conv3mma_kernel<64, 32, 256, 1>,
                         cudaFuncAttributeMaxDynamicSharedMemorySize, SMEM2);

    // 0) weight prep
    permute_w_kernel<<<(8 * 128 * 96 + 255) / 256, 256, 0, st>>>(w_tr1, w2a, 8, 128, 96);
    permute_w_kernel<<<(8 * 64 * 64 + 255) / 256, 256, 0, st>>>(w_tr2, w2b, 8, 64, 64);
    wfrag_kernel<<<(27 * 12 * 8 * 32 + 255) / 256, 256, 0, st>>>(w_c1, wf1, 96, 64);
    wfrag_kernel<<<(27 * 8 * 4 * 32 + 255) / 256, 256, 0, st>>>(w_c2, wf2, 64, 32);

    // 1) convtr2_1: [8000,128]@[128,768] -> t1 viewed [64000,96]
    {
        dim3 grid(768 / GBN, (N0 + GBM - 1) / GBM);
        gemm_kernel<<<grid, 256, 0, st>>>(x, w2a, t1, N0, 768, 128);
    }
    run_stats(t1, N1, 96, g1, b1, part, ab, st);
    bnrelu4_kernel<<<(N1 * 96 / 4 + 255) / 256, 256, 0, st>>>(t1, ab, N1 * 96 / 4, 96);

    // 2) conv3_1: [64000,96] -> [64000,64]  (tf32 mma, BM=128)
    conv3mma_kernel<96, 64, 128, 2><<<N1 / 128, 256, SMEM1, st>>>(t1, idx1, mask1, wf1, t2, N1);
    run_stats(t2, N1, 64, g2, b2, part, ab, st);
    bnrelu4_kernel<<<(N1 * 64 / 4 + 255) / 256, 256, 0, st>>>(t2, ab, N1 * 64 / 4, 64);

    // 3) convtr2_2: [64000,64]@[64,512] -> t3 viewed [512000,64]
    {
        dim3 grid(512 / GBN, N1 / GBM);
        gemm_kernel<<<grid, 256, 0, st>>>(t2, w2b, t3, N1, 512, 64);
    }
    run_stats(t3, N2, 64, g3, b3, part, ab, st);
    bnrelu4_kernel<<<(N2 * 64 / 4 + 255) / 256, 256, 0, st>>>(t3, ab, N2 * 64 / 4, 64);

    // 4) conv3_2: [512000,64] -> [512000,32]  (tf32 mma, BM=256)
    conv3mma_kernel<64, 32, 256, 1><<<N2 / 256, 256, SMEM2, st>>>(t3, idx2, mask2, wf2, t4, N2);
    run_stats(t4, N2, 32, g4, b4, part, ab, st);
    bnrelu_rowmean32_kernel<<<(N2 + 7) / 8, 256, 0, st>>>(t4, ab, out, N2);

    // 5) decoder: [512000,32]@[32,96] -> out+512000 (pre-BN), then BN+ReLU in place
    float* seg = out + N2;
    dec_kernel<<<N2 / 64, 384, 0, st>>>(t4, w_dec, seg, N2);
    run_stats(seg, N2, 96, g5, b5, part, ab, st);
    bnrelu4_kernel<<<(N2 * 96 / 4 + 255) / 256, 256, 0, st>>>(seg, ab, N2 * 96 / 4, 96);
}

// round 10
// speedup vs baseline: 1.0137x; 1.0002x over previous
#include <cuda_runtime.h>
#include <cuda_bf16.h>
#include <cstdint>

// ---------------- constants ----------------
#define N0 8000
#define N1 64000
#define N2 512000
#define NBLK_STATS 512

// ---------------- device scratch (no allocations allowed) ----------------
__device__ float g_t1[N1 * 96];        // layer1 out  [64000, 96]
__device__ float g_t2[N1 * 64];        // layer2 out  [64000, 64]
__device__ float g_t3[N2 * 64];        // layer3 out  [512000, 64]
__device__ float g_t4[N2 * 32];        // layer4 out  [512000, 32]
__device__ float g_w2a[128 * 8 * 96];  // permuted w_tr1 -> [128, 768]
__device__ float g_w2b[64 * 8 * 64];   // permuted w_tr2 -> [64, 512]
__device__ float g_wf1[27 * 96 * 64];  // w_c1 in tf32 fragment order
__device__ float g_wf2[27 * 64 * 32];  // w_c2 in tf32 fragment order
__device__ float g_part[NBLK_STATS * 2 * 96];
__device__ float g_ab[2 * 96];         // folded BN scale/shift

// ---------------- helpers ----------------
__device__ __forceinline__ uint32_t f2tf32(float f) {
    uint32_t u;
    asm("cvt.rna.tf32.f32 %0, %1;" : "=r"(u) : "f"(f));
    return u;
}

__device__ __forceinline__ void mma_tf32(float c[4], uint32_t a0, uint32_t a1,
                                         uint32_t a2, uint32_t a3,
                                         uint32_t b0, uint32_t b1) {
    asm("mma.sync.aligned.m16n8k8.row.col.f32.tf32.tf32.f32 "
        "{%0,%1,%2,%3},{%4,%5,%6,%7},{%8,%9},{%0,%1,%2,%3};"
        : "+f"(c[0]), "+f"(c[1]), "+f"(c[2]), "+f"(c[3])
        : "r"(a0), "r"(a1), "r"(a2), "r"(a3), "r"(b0), "r"(b1));
}

// ---------------- weight permute: w[k,c,d] -> W2[c, k*D+d] ----------------
__global__ void permute_w_kernel(const float* __restrict__ w, float* __restrict__ W2,
                                 int KK, int Cin, int D) {
    int t = blockIdx.x * blockDim.x + threadIdx.x;
    int tot = KK * Cin * D;
    if (t >= tot) return;
    int d = t % D;
    int c = (t / D) % Cin;
    int k = t / (D * Cin);
    W2[c * (KK * D) + k * D + d] = w[t];
}

// ---------------- wfrag prep: w[27,CIN,COUT] -> tf32 fragment order -------------
// wf[((k*KS + kk)*NFT + nf)*64 + lane*2 + {0,1}]
//   b0 = w[k][kk*8 + lane%4    ][nf*8 + lane/4]
//   b1 = w[k][kk*8 + lane%4 + 4][nf*8 + lane/4]
__global__ void wfrag_kernel(const float* __restrict__ w, float* __restrict__ wf,
                             int CIN, int COUT) {
    int t = blockIdx.x * blockDim.x + threadIdx.x;
    int KS = CIN / 8, NFT = COUT / 8;
    int tot = 27 * KS * NFT * 32;
    if (t >= tot) return;
    int lane = t & 31;
    int rest = t >> 5;
    int nf = rest % NFT; rest /= NFT;
    int kk = rest % KS;
    int k = rest / KS;
    int row = kk * 8 + (lane & 3);
    int col = nf * 8 + (lane >> 2);
    const float* wk = w + (size_t)k * CIN * COUT;
    wf[2 * t + 0] = __uint_as_float(f2tf32(wk[(size_t)row * COUT + col]));
    wf[2 * t + 1] = __uint_as_float(f2tf32(wk[(size_t)(row + 4) * COUT + col]));
}

// ---------------- fp32 tiled GEMM: C[M,N] = A[M,K] @ B[K,N] ----------------
#define GBM 64
#define GBN 64
#define GBK 16
#define GPITCH 68
__global__ __launch_bounds__(256) void gemm_kernel(const float* __restrict__ A,
                                                   const float* __restrict__ B,
                                                   float* __restrict__ C,
                                                   int M, int N, int K) {
    __shared__ __align__(16) float As[GBK][GPITCH];
    __shared__ __align__(16) float Bs[GBK][GBN];
    const int tid = threadIdx.x;
    const int tx = tid % 16;
    const int ty = tid / 16;
    const int rowBase = blockIdx.y * GBM;
    const int colBase = blockIdx.x * GBN;
    float acc[4][4] = {};
    for (int k0 = 0; k0 < K; k0 += GBK) {
        #pragma unroll
        for (int t = tid; t < GBM * GBK; t += 256) {
            int c = t % GBK, r = t / GBK;
            int gr = rowBase + r, gc = k0 + c;
            As[c][r] = (gr < M && gc < K) ? A[(size_t)gr * K + gc] : 0.f;
        }
        #pragma unroll
        for (int t = tid; t < GBK * GBN; t += 256) {
            int c = t % GBN, r = t / GBN;
            int gr = k0 + r, gc = colBase + c;
            Bs[r][c] = (gr < K && gc < N) ? B[(size_t)gr * N + gc] : 0.f;
        }
        __syncthreads();
        #pragma unroll
        for (int kk = 0; kk < GBK; kk++) {
            float4 av = *reinterpret_cast<const float4*>(&As[kk][ty * 4]);
            float4 bv = *reinterpret_cast<const float4*>(&Bs[kk][tx * 4]);
            float a[4] = {av.x, av.y, av.z, av.w};
            float b[4] = {bv.x, bv.y, bv.z, bv.w};
            #pragma unroll
            for (int i = 0; i < 4; i++)
                #pragma unroll
                for (int j = 0; j < 4; j++) acc[i][j] = fmaf(a[i], b[j], acc[i][j]);
        }
        __syncthreads();
    }
    #pragma unroll
    for (int i = 0; i < 4; i++) {
        int gr = rowBase + ty * 4 + i;
        if (gr >= M) continue;
        #pragma unroll
        for (int j = 0; j < 4; j++) {
            int gc = colBase + tx * 4 + j;
            if (gc < N) C[(size_t)gr * N + gc] = acc[i][j];
        }
    }
}

// ---------------- BN stats: per-block column sum/sumsq, float4, deterministic ------
__global__ void stats4_kernel(const float* __restrict__ X, int nrows, int C,
                              float* __restrict__ part) {
    extern __shared__ float sm[];
    const int C4 = C >> 2;
    const int c4 = threadIdx.x;
    const int ty = threadIdx.y;
    const int TY = blockDim.y;
    const float4* X4 = reinterpret_cast<const float4*>(X);
    float s0 = 0.f, s1 = 0.f, s2 = 0.f, s3 = 0.f;
    float q0 = 0.f, q1 = 0.f, q2 = 0.f, q3 = 0.f;
    for (int n = blockIdx.x * TY + ty; n < nrows; n += gridDim.x * TY) {
        float4 v = X4[(size_t)n * C4 + c4];
        s0 += v.x; q0 = fmaf(v.x, v.x, q0);
        s1 += v.y; q1 = fmaf(v.y, v.y, q1);
        s2 += v.z; q2 = fmaf(v.z, v.z, q2);
        s3 += v.w; q3 = fmaf(v.w, v.w, q3);
    }
    float* S = sm;
    float* Q = sm + TY * C;
    int cb = c4 * 4;
    S[ty * C + cb + 0] = s0; S[ty * C + cb + 1] = s1;
    S[ty * C + cb + 2] = s2; S[ty * C + cb + 3] = s3;
    Q[ty * C + cb + 0] = q0; Q[ty * C + cb + 1] = q1;
    Q[ty * C + cb + 2] = q2; Q[ty * C + cb + 3] = q3;
    __syncthreads();
    int tid = ty * C4 + c4;
    if (tid < C) {
        float s = 0.f, q = 0.f;
        for (int t = 0; t < TY; t++) { s += S[t * C + tid]; q += Q[t * C + tid]; }
        part[blockIdx.x * 2 * C + tid] = s;
        part[blockIdx.x * 2 * C + C + tid] = q;
    }
}

// ---------------- finalize: fold BN into a[c], b'[c] ----------------
__global__ void finalize_kernel(const float* __restrict__ part, int nblk, int C,
                                float invN, const float* __restrict__ g,
                                const float* __restrict__ b, float* __restrict__ ab) {
    int c = threadIdx.x;
    if (c >= C) return;
    float s = 0.f, q = 0.f;
    #pragma unroll 8
    for (int i = 0; i < nblk; i++) {
        s += part[i * 2 * C + c];
        q += part[i * 2 * C + C + c];
    }
    float mean = s * invN;
    float var = q * invN - mean * mean;
    float rstd = rsqrtf(var + 1e-5f);
    float a = g[c] * rstd;
    ab[c] = a;
    ab[C + c] = b[c] - mean * a;
}

// ---------------- BN apply + ReLU (in place, float4) ----------------
__global__ void bnrelu4_kernel(float* __restrict__ X, const float* __restrict__ ab,
                               int total4, int C) {
    int t = blockIdx.x * blockDim.x + threadIdx.x;
    if (t >= total4) return;
    int C4 = C >> 2;
    int c = (t % C4) * 4;
    float4 v = reinterpret_cast<float4*>(X)[t];
    v.x = fmaxf(fmaf(v.x, __ldg(ab + c + 0), __ldg(ab + C + c + 0)), 0.f);
    v.y = fmaxf(fmaf(v.y, __ldg(ab + c + 1), __ldg(ab + C + c + 1)), 0.f);
    v.z = fmaxf(fmaf(v.z, __ldg(ab + c + 2), __ldg(ab + C + c + 2)), 0.f);
    v.w = fmaxf(fmaf(v.w, __ldg(ab + c + 3), __ldg(ab + C + c + 3)), 0.f);
    reinterpret_cast<float4*>(X)[t] = v;
}

// ---------------- BN apply + ReLU + row-mean (layer 4, C=32) ----------------
__global__ void bnrelu_rowmean32_kernel(float* __restrict__ X, const float* __restrict__ ab,
                                        float* __restrict__ intensity, int N) {
    int gw = (blockIdx.x * blockDim.x + threadIdx.x) >> 5;
    int lane = threadIdx.x & 31;
    if (gw >= N) return;
    float v = fmaxf(fmaf(X[(size_t)gw * 32 + lane], ab[lane], ab[32 + lane]), 0.f);
    X[(size_t)gw * 32 + lane] = v;
    float s = v;
    #pragma unroll
    for (int o = 16; o; o >>= 1) s += __shfl_xor_sync(0xFFFFFFFFu, s, o);
    if (lane == 0) intensity[gw] = s * (1.f / 32.f);
}

// ---------------- conv3 via tf32 mma.sync gather-GEMM ----------------------
// Block: BM rows. 8 warps, each computes a 32 x (COUT/NWARP) tile.
// Per offset k: gather BM rows (mask-scaled, tf32-rounded) into SMEM As
// [BM][CIN+4], stage pre-fragmented W[k] slice, run m16n8k8 MMAs.
template <int CIN, int COUT, int BM, int NWARP>
__global__ __launch_bounds__(256) void conv3mma_kernel(
    const float* __restrict__ X, const int* __restrict__ idx,
    const float* __restrict__ mask, const float* __restrict__ Wf,
    float* __restrict__ out, int N) {
    constexpr int PITCH = CIN + 4;
    constexpr int C4 = CIN / 4;
    constexpr int KS = CIN / 8;
    constexpr int NFT = COUT / 8;
    constexpr int NPW = COUT / NWARP;   // cols per warp
    constexpr int NF = NPW / 8;         // n-frags per warp
    constexpr int ROWTILES = BM / 32;
    static_assert(ROWTILES * NWARP == 8, "need 8 warps");

    extern __shared__ __align__(16) char smem_raw[];
    uint32_t* As = reinterpret_cast<uint32_t*>(smem_raw);            // BM*PITCH
    float* Wfs = reinterpret_cast<float*>(As + BM * PITCH);          // CIN*COUT
    int* ridx = reinterpret_cast<int*>(Wfs + CIN * COUT);            // BM
    float* rmask = reinterpret_cast<float*>(ridx + BM);              // BM

    const int tid = threadIdx.x;
    const int w = tid >> 5;
    const int lane = tid & 31;
    const int lr = lane >> 2;   // groupID
    const int lc = lane & 3;    // thread in group
    const int rowtile = w / NWARP;
    const int nhalf = w % NWARP;
    const int rowbase = rowtile * 32;
    const int n0 = blockIdx.x * BM;
    const float4* X4 = reinterpret_cast<const float4*>(X);

    float acc[2][NF][4];
    #pragma unroll
    for (int mf = 0; mf < 2; mf++)
        #pragma unroll
        for (int nf = 0; nf < NF; nf++)
            #pragma unroll
            for (int i = 0; i < 4; i++) acc[mf][nf][i] = 0.f;

    for (int k = 0; k < 27; k++) {
        __syncthreads();  // previous compute done; As/Wfs/ridx reusable
        if (tid < BM) {
            int n = n0 + tid;
            ridx[tid] = idx[(size_t)k * N + n];
            rmask[tid] = mask[(size_t)k * N + n];
        }
        {
            const float4* src = reinterpret_cast<const float4*>(Wf + (size_t)k * CIN * COUT);
            float4* dst = reinterpret_cast<float4*>(Wfs);
            #pragma unroll
            for (int t = tid; t < CIN * COUT / 4; t += 256) dst[t] = src[t];
        }
        __syncthreads();  // ridx/rmask visible
        // gather + mask + tf32 round
        #pragma unroll
        for (int t = tid; t < BM * C4; t += 256) {
            int r = t / C4, c4 = t % C4;
            float4 v = X4[(size_t)ridx[r] * C4 + c4];
            float m = rmask[r];
            uint4 u;
            u.x = f2tf32(v.x * m);
            u.y = f2tf32(v.y * m);
            u.z = f2tf32(v.z * m);
            u.w = f2tf32(v.w * m);
            *reinterpret_cast<uint4*>(As + r * PITCH + c4 * 4) = u;
        }
        __syncthreads();  // As visible
        // MMA over K
        const uint2* Wu = reinterpret_cast<const uint2*>(Wfs);
        #pragma unroll
        for (int ks = 0; ks < KS; ks++) {
            uint32_t a[2][4];
            #pragma unroll
            for (int mf = 0; mf < 2; mf++) {
                int base = (rowbase + mf * 16 + lr) * PITCH + ks * 8 + lc;
                a[mf][0] = As[base];
                a[mf][1] = As[base + 8 * PITCH];
                a[mf][2] = As[base + 4];
                a[mf][3] = As[base + 8 * PITCH + 4];
            }
            #pragma unroll
            for (int nf = 0; nf < NF; nf++) {
                uint2 b = Wu[(ks * NFT + nhalf * NF + nf) * 32 + lane];
                #pragma unroll
                for (int mf = 0; mf < 2; mf++)
                    mma_tf32(acc[mf][nf], a[mf][0], a[mf][1], a[mf][2], a[mf][3], b.x, b.y);
            }
        }
    }
    // epilogue
    #pragma unroll
    for (int mf = 0; mf < 2; mf++) {
        int row0 = n0 + rowbase + mf * 16 + lr;
        #pragma unroll
        for (int nf = 0; nf < NF; nf++) {
            int col = nhalf * NPW + nf * 8 + lc * 2;
            float2 lo = make_float2(acc[mf][nf][0], acc[mf][nf][1]);
            float2 hi = make_float2(acc[mf][nf][2], acc[mf][nf][3]);
            *reinterpret_cast<float2*>(out + (size_t)row0 * COUT + col) = lo;
            *reinterpret_cast<float2*>(out + (size_t)(row0 + 8) * COUT + col) = hi;
        }
    }
}

// ---------------- decoder: [N,32] @ [32,96] -> [N,96], BM=64, 384 thr ----------
__global__ __launch_bounds__(384) void dec_kernel(const float* __restrict__ A,
                                                  const float* __restrict__ W,
                                                  float* __restrict__ C_, int N) {
    constexpr int K = 32, COUT = 96, BM = 64, PITCH = BM + 1;
    constexpr int TX = COUT / 4;  // 24
    __shared__ float As[K][PITCH];
    __shared__ __align__(16) float Bs[K][COUT];
    const int tid = threadIdx.x;
    const int tx = tid % TX;
    const int ty = tid / TX;
    const int n0 = blockIdx.x * BM;

    {
        const float4* W4 = reinterpret_cast<const float4*>(W);
        float4* bs4 = reinterpret_cast<float4*>(&Bs[0][0]);
        #pragma unroll
        for (int t = tid; t < K * COUT / 4; t += 384) bs4[t] = W4[t];
    }
    #pragma unroll
    for (int i = tid; i < BM * (K / 4); i += 384) {
        int r = i & (BM - 1), c4 = i / BM;
        float4 v = *reinterpret_cast<const float4*>(A + (size_t)(n0 + r) * K + c4 * 4);
        As[c4 * 4 + 0][r] = v.x;
        As[c4 * 4 + 1][r] = v.y;
        As[c4 * 4 + 2][r] = v.z;
        As[c4 * 4 + 3][r] = v.w;
    }
    __syncthreads();

    float acc[4][4] = {};
    #pragma unroll 8
    for (int kk = 0; kk < K; kk++) {
        float a[4], b[4];
        #pragma unroll
        for (int i = 0; i < 4; i++) a[i] = As[kk][ty * 4 + i];
        float4 bv = *reinterpret_cast<const float4*>(&Bs[kk][tx * 4]);
        b[0] = bv.x; b[1] = bv.y; b[2] = bv.z; b[3] = bv.w;
        #pragma unroll
        for (int i = 0; i < 4; i++)
            #pragma unroll
            for (int j = 0; j < 4; j++) acc[i][j] = fmaf(a[i], b[j], acc[i][j]);
    }
    #pragma unroll
    for (int i = 0; i < 4; i++) {
        int n = n0 + ty * 4 + i;
        float4 o = make_float4(acc[i][0], acc[i][1], acc[i][2], acc[i][3]);
        *reinterpret_cast<float4*>(C_ + (size_t)n * COUT + tx * 4) = o;
    }
}

// ---------------- host driver ----------------
static inline void run_stats(const float* X, int N, int C,
                             const float* g, const float* b,
                             float* part, float* ab, cudaStream_t st) {
    int C4 = C / 4;
    int TY = 256 / C4;
    dim3 blk(C4, TY);
    size_t sm = (size_t)2 * C * TY * sizeof(float);
    stats4_kernel<<<NBLK_STATS, blk, sm, st>>>(X, N, C, part);
    finalize_kernel<<<1, C, 0, st>>>(part, NBLK_STATS, C, 1.0f / (float)N, g, b, ab);
}

extern "C" void kernel_launch(void* const* d_in, const int* in_sizes, int n_in,
                              void* d_out, int out_size) {
    const float* x     = (const float*)d_in[0];
    const float* w_tr1 = (const float*)d_in[1];
    const float* g1    = (const float*)d_in[2];
    const float* b1    = (const float*)d_in[3];
    const int*   idx1  = (const int*)  d_in[4];
    const float* mask1 = (const float*)d_in[5];
    const float* w_c1  = (const float*)d_in[6];
    const float* g2    = (const float*)d_in[7];
    const float* b2    = (const float*)d_in[8];
    const float* w_tr2 = (const float*)d_in[9];
    const float* g3    = (const float*)d_in[10];
    const float* b3    = (const float*)d_in[11];
    const int*   idx2  = (const int*)  d_in[12];
    const float* mask2 = (const float*)d_in[13];
    const float* w_c2  = (const float*)d_in[14];
    const float* g4    = (const float*)d_in[15];
    const float* b4    = (const float*)d_in[16];
    const float* w_dec = (const float*)d_in[17];
    const float* g5    = (const float*)d_in[18];
    const float* b5    = (const float*)d_in[19];
    float* out = (float*)d_out;

    float *t1, *t2, *t3, *t4, *w2a, *w2b, *wf1, *wf2, *part, *ab;
    cudaGetSymbolAddress((void**)&t1, g_t1);
    cudaGetSymbolAddress((void**)&t2, g_t2);
    cudaGetSymbolAddress((void**)&t3, g_t3);
    cudaGetSymbolAddress((void**)&t4, g_t4);
    cudaGetSymbolAddress((void**)&w2a, g_w2a);
    cudaGetSymbolAddress((void**)&w2b, g_w2b);
    cudaGetSymbolAddress((void**)&wf1, g_wf1);
    cudaGetSymbolAddress((void**)&wf2, g_wf2);
    cudaGetSymbolAddress((void**)&part, g_part);
    cudaGetSymbolAddress((void**)&ab, g_ab);

    cudaStream_t st = 0;

    // smem opt-in for the mma conv kernels (idempotent, host-side, capture-safe)
    const int SMEM1 = 128 * (96 + 4) * 4 + 96 * 64 * 4 + 128 * 8;   // 77,824
    const int SMEM2 = 256 * (64 + 4) * 4 + 64 * 32 * 4 + 256 * 8;   // 79,872
    cudaFuncSetAttribute(conv3mma_kernel<96, 64, 128, 2>,
                         cudaFuncAttributeMaxDynamicSharedMemorySize, SMEM1);
    cudaFuncSetAttribute(conv3mma_kernel<64, 32, 256, 1>,
                         cudaFuncAttributeMaxDynamicSharedMemorySize, SMEM2);

    // 0) weight prep
    permute_w_kernel<<<(8 * 128 * 96 + 255) / 256, 256, 0, st>>>(w_tr1, w2a, 8, 128, 96);
    permute_w_kernel<<<(8 * 64 * 64 + 255) / 256, 256, 0, st>>>(w_tr2, w2b, 8, 64, 64);
    wfrag_kernel<<<(27 * 12 * 8 * 32 + 255) / 256, 256, 0, st>>>(w_c1, wf1, 96, 64);
    wfrag_kernel<<<(27 * 8 * 4 * 32 + 255) / 256, 256, 0, st>>>(w_c2, wf2, 64, 32);

    // 1) convtr2_1: [8000,128]@[128,768] -> t1 viewed [64000,96]
    {
        dim3 grid(768 / GBN, (N0 + GBM - 1) / GBM);
        gemm_kernel<<<grid, 256, 0, st>>>(x, w2a, t1, N0, 768, 128);
    }
    run_stats(t1, N1, 96, g1, b1, part, ab, st);
    bnrelu4_kernel<<<(N1 * 96 / 4 + 255) / 256, 256, 0, st>>>(t1, ab, N1 * 96 / 4, 96);

    // 2) conv3_1: [64000,96] -> [64000,64]  (tf32 mma, BM=128)
    conv3mma_kernel<96, 64, 128, 2><<<N1 / 128, 256, SMEM1, st>>>(t1, idx1, mask1, wf1, t2, N1);
    run_stats(t2, N1, 64, g2, b2, part, ab, st);
    bnrelu4_kernel<<<(N1 * 64 / 4 + 255) / 256, 256, 0, st>>>(t2, ab, N1 * 64 / 4, 64);

    // 3) convtr2_2: [64000,64]@[64,512] -> t3 viewed [512000,64]
    {
        dim3 grid(512 / GBN, N1 / GBM);
        gemm_kernel<<<grid, 256, 0, st>>>(t2, w2b, t3, N1, 512, 64);
    }
    run_stats(t3, N2, 64, g3, b3, part, ab, st);
    bnrelu4_kernel<<<(N2 * 64 / 4 + 255) / 256, 256, 0, st>>>(t3, ab, N2 * 64 / 4, 64);

    // 4) conv3_2: [512000,64] -> [512000,32]  (tf32 mma, BM=256)
    conv3mma_kernel<64, 32, 256, 1><<<N2 / 256, 256, SMEM2, st>>>(t3, idx2, mask2, wf2, t4, N2);
    run_stats(t4, N2, 32, g4, b4, part, ab, st);
    bnrelu_rowmean32_kernel<<<(N2 + 7) / 8, 256, 0, st>>>(t4, ab, out, N2);

    // 5) decoder: [512000,32]@[32,96] -> out+512000 (pre-BN), then BN+ReLU in place
    float* seg = out + N2;
    dec_kernel<<<N2 / 64, 384, 0, st>>>(t4, w_dec, seg, N2);
    run_stats(seg, N2, 96, g5, b5, part, ab, st);
    bnrelu4_kernel<<<(N2 * 96 / 4 + 255) / 256, 256, 0, st>>>(seg, ab, N2 * 96 / 4, 96);
}